// round 1
// baseline (speedup 1.0000x reference)
#include <cuda_runtime.h>

#define B_TOT   16384
#define TM      16
#define NTHR    192
#define NSTEPS_ 10

typedef unsigned long long u64;

__device__ __forceinline__ u64 pk2(float lo, float hi) {
    u64 r; asm("mov.b64 %0,{%1,%2};" : "=l"(r) : "f"(lo), "f"(hi)); return r;
}
__device__ __forceinline__ float2 upk2(u64 v) {
    float2 f; asm("mov.b64 {%0,%1},%2;" : "=f"(f.x), "=f"(f.y) : "l"(v)); return f;
}
__device__ __forceinline__ void fma2(u64& d, u64 a, u64 b) {
    asm("fma.rn.f32x2 %0,%1,%2,%0;" : "+l"(d) : "l"(a), "l"(b));
}

// Shared layout (floats):
//   [0,36864)      W2s   192x192
//   [36864,43776)  shA   192x36  (aliased: hS 256x16, a2t 32x196)
//   [43776,46848)  shHC  192x16
//   [46848,49920)  shW1a 16x192
//   [49920,50112)  shW1t 192
//   [50112,50304)  shB2  192
//   [50304,53376)  shW3t 16x192
//   [53376,53392)  shB3  16
//   [53392,53968)  shYE  16x36
//   [53968,54512)  shFJ  32x17
//   [54512,55280)  shFB  3x256
//   [55280,55536)  shY   16x16
//   [55536,55552)  shTR  16
#define SMEM_FLOATS 55552

__global__ __launch_bounds__(NTHR, 1)
void ConditionalCNF_27590869910221_kernel(
    const float* __restrict__ theta, const float* __restrict__ hg,
    const float* __restrict__ eps,   const float* __restrict__ W1,
    const float* __restrict__ b1,    const float* __restrict__ W2,
    const float* __restrict__ b2,    const float* __restrict__ W3,
    const float* __restrict__ b3,    float* __restrict__ out)
{
    extern __shared__ float sm[];
    float* shW2  = sm;
    float* shA   = sm + 36864;
    float* shHC  = sm + 43776;
    float* shW1a = sm + 46848;
    float* shW1t = sm + 49920;
    float* shB2  = sm + 50112;
    float* shW3t = sm + 50304;
    float* shB3  = sm + 53376;
    float* shYE  = sm + 53392;
    float* shFJ  = sm + 53968;
    float* shFB  = sm + 54512;
    float* shY   = sm + 55280;
    float* shTR  = sm + 55536;

    const int tid = threadIdx.x;
    const int u = tid % 96, g = tid / 96;   // u: j-pair index, g: sample half
    const int j0 = 2 * u;
    const int s0 = blockIdx.x * TM;
    const float dtf = -0.1f;

    // ---------------- phase 0: stage weights / state ----------------
    {
        const float4* W2g4 = (const float4*)W2;
        float4* shW24 = (float4*)shW2;
        for (int i = tid; i < 36864 / 4; i += NTHR) shW24[i] = W2g4[i];
        for (int i = tid; i < 3072; i += NTHR) shW1a[i] = W1[i];           // rows 0..15
        for (int i = tid; i < 192; i += NTHR) {
            shW1t[i] = W1[272 * 192 + i];                                  // t row
            shB2[i]  = b2[i];
        }
        for (int i = tid; i < 3072; i += NTHR) {                           // W3 transpose
            int k = i >> 4, dd = i & 15;
            shW3t[dd * 192 + k] = W3[i];
        }
        if (tid < 16) { shB3[tid] = b3[tid]; shTR[tid] = 0.f; }
        for (int i = tid; i < 256; i += NTHR) shY[i] = theta[s0 * 16 + i];
        // h tile into shA as hS[c][s], row stride 16
        const float4* hg4 = (const float4*)hg;
        for (int i = tid; i < 1024; i += NTHR) {
            float4 v = hg4[s0 * 64 + i];
            int s = i >> 6, c = (i & 63) * 4;
            shA[(c + 0) * 16 + s] = v.x; shA[(c + 1) * 16 + s] = v.y;
            shA[(c + 2) * 16 + s] = v.z; shA[(c + 3) * 16 + s] = v.w;
        }
    }
    __syncthreads();

    // ---------------- hc = b1 + h @ W1[16:272,:] ----------------
    {
        u64 acc[2][4];
        float bj0 = b1[j0], bj1 = b1[j0 + 1];
        u64 p0 = pk2(bj0, bj0), p1 = pk2(bj1, bj1);
        #pragma unroll
        for (int p = 0; p < 4; p++) { acc[0][p] = p0; acc[1][p] = p1; }
        const float* hrow = shA + g * 8;
        #pragma unroll 4
        for (int k = 0; k < 256; k++) {
            float2 w = *(const float2*)(W1 + (16 + k) * 192 + j0);         // L2-resident
            u64 w0 = pk2(w.x, w.x), w1 = pk2(w.y, w.y);
            const ulonglong2* ap = (const ulonglong2*)(hrow + k * 16);
            ulonglong2 A0 = ap[0], A1 = ap[1];
            fma2(acc[0][0], A0.x, w0); fma2(acc[0][1], A0.y, w0);
            fma2(acc[0][2], A1.x, w0); fma2(acc[0][3], A1.y, w0);
            fma2(acc[1][0], A0.x, w1); fma2(acc[1][1], A0.y, w1);
            fma2(acc[1][2], A1.x, w1); fma2(acc[1][3], A1.y, w1);
        }
        #pragma unroll
        for (int jj = 0; jj < 2; jj++)
            #pragma unroll
            for (int p = 0; p < 4; p++) {
                float2 v = upk2(acc[jj][p]);
                shHC[(j0 + jj) * 16 + g * 8 + 2 * p]     = v.x;
                shHC[(j0 + jj) * 16 + g * 8 + 2 * p + 1] = v.y;
            }
    }
    __syncthreads();

    const float kSQ = 0.70710678118654752f;    // 1/sqrt(2)
    const float kPDF = 0.3989422804014327f;    // 1/sqrt(2*pi)

    u64 aA[2][4], aD[2][4];

    for (int step = 0; step < NSTEPS_; step++) {
        float t0 = 1.0f + dtf * (float)step;
        for (int st = 0; st < 4; st++) {
            float tc = t0 + dtf * (st == 0 ? 0.f : st == 1 ? (1.f / 3.f)
                                 : st == 2 ? (2.f / 3.f) : 1.f);

            // ---- phase A: stage y + eps into shYE ----
            for (int i = tid; i < 256; i += NTHR) {
                int s = i >> 4, d = i & 15;
                float e = eps[(((step * 4 + st) * B_TOT) + s0 + s) * 16 + d];
                shYE[d * 36 + 16 + s] = e;
                float yb = shY[i];
                float yc;
                if      (st == 0) yc = yb;
                else if (st == 1) yc = yb + (dtf * (1.f / 3.f)) * shFB[i];
                else if (st == 2) yc = yb + dtf * (shFB[256 + i] - (1.f / 3.f) * shFB[i]);
                else              yc = yb + dtf * (shFB[i] - shFB[256 + i] + shFB[512 + i]);
                shYE[d * 36 + s] = yc;
            }
            __syncthreads();

            // ---- layer 1: z1 = hc + t*W1t + y@W1a ; dz1 = e@W1a ----
            #pragma unroll
            for (int jj = 0; jj < 2; jj++) {
                float tw = tc * shW1t[j0 + jj];
                const float* hcp = shHC + (j0 + jj) * 16 + g * 8;
                #pragma unroll
                for (int p = 0; p < 4; p++) {
                    aA[jj][p] = pk2(hcp[2 * p] + tw, hcp[2 * p + 1] + tw);
                    aD[jj][p] = 0ull;
                }
            }
            #pragma unroll
            for (int k = 0; k < 16; k++) {
                const float* ar = shYE + k * 36 + g * 8;
                ulonglong2 A0 = *(const ulonglong2*)ar;
                ulonglong2 A1 = *(const ulonglong2*)(ar + 4);
                ulonglong2 E0 = *(const ulonglong2*)(ar + 16);
                ulonglong2 E1 = *(const ulonglong2*)(ar + 20);
                float2 w = *(const float2*)(shW1a + k * 192 + j0);
                u64 w0 = pk2(w.x, w.x), w1 = pk2(w.y, w.y);
                fma2(aA[0][0], A0.x, w0); fma2(aA[0][1], A0.y, w0);
                fma2(aA[0][2], A1.x, w0); fma2(aA[0][3], A1.y, w0);
                fma2(aA[1][0], A0.x, w1); fma2(aA[1][1], A0.y, w1);
                fma2(aA[1][2], A1.x, w1); fma2(aA[1][3], A1.y, w1);
                fma2(aD[0][0], E0.x, w0); fma2(aD[0][1], E0.y, w0);
                fma2(aD[0][2], E1.x, w0); fma2(aD[0][3], E1.y, w0);
                fma2(aD[1][0], E0.x, w1); fma2(aD[1][1], E0.y, w1);
                fma2(aD[1][2], E1.x, w1); fma2(aD[1][3], E1.y, w1);
            }

            // GELU layer1 + store a1/d1 rows
            #pragma unroll
            for (int jj = 0; jj < 2; jj++) {
                float va[8], vd[8];
                #pragma unroll
                for (int p = 0; p < 4; p++) {
                    float2 z  = upk2(aA[jj][p]);
                    float2 dz = upk2(aD[jj][p]);
                    float c0 = 0.5f * (1.f + erff(z.x * kSQ));
                    float c1 = 0.5f * (1.f + erff(z.y * kSQ));
                    va[2 * p]     = z.x * c0;
                    va[2 * p + 1] = z.y * c1;
                    float g0 = c0 + z.x * kPDF * __expf(-0.5f * z.x * z.x);
                    float g1 = c1 + z.y * kPDF * __expf(-0.5f * z.y * z.y);
                    vd[2 * p]     = g0 * dz.x;
                    vd[2 * p + 1] = g1 * dz.y;
                }
                float* row = shA + (j0 + jj) * 36 + g * 8;
                *(float4*)(row)      = make_float4(va[0], va[1], va[2], va[3]);
                *(float4*)(row + 4)  = make_float4(va[4], va[5], va[6], va[7]);
                *(float4*)(row + 16) = make_float4(vd[0], vd[1], vd[2], vd[3]);
                *(float4*)(row + 20) = make_float4(vd[4], vd[5], vd[6], vd[7]);
            }
            __syncthreads();

            // ---- layer 2: z2 = a1@W2 + b2 ; dz2 = d1@W2 ----
            #pragma unroll
            for (int jj = 0; jj < 2; jj++) {
                float bb = shB2[j0 + jj];
                u64 bp = pk2(bb, bb);
                #pragma unroll
                for (int p = 0; p < 4; p++) { aA[jj][p] = bp; aD[jj][p] = 0ull; }
            }
            #pragma unroll 8
            for (int k = 0; k < 192; k++) {
                const float* ar = shA + k * 36 + g * 8;
                ulonglong2 A0 = *(const ulonglong2*)ar;
                ulonglong2 A1 = *(const ulonglong2*)(ar + 4);
                ulonglong2 E0 = *(const ulonglong2*)(ar + 16);
                ulonglong2 E1 = *(const ulonglong2*)(ar + 20);
                float2 w = *(const float2*)(shW2 + k * 192 + j0);
                u64 w0 = pk2(w.x, w.x), w1 = pk2(w.y, w.y);
                fma2(aA[0][0], A0.x, w0); fma2(aA[0][1], A0.y, w0);
                fma2(aA[0][2], A1.x, w0); fma2(aA[0][3], A1.y, w0);
                fma2(aA[1][0], A0.x, w1); fma2(aA[1][1], A0.y, w1);
                fma2(aA[1][2], A1.x, w1); fma2(aA[1][3], A1.y, w1);
                fma2(aD[0][0], E0.x, w0); fma2(aD[0][1], E0.y, w0);
                fma2(aD[0][2], E1.x, w0); fma2(aD[0][3], E1.y, w0);
                fma2(aD[1][0], E0.x, w1); fma2(aD[1][1], E0.y, w1);
                fma2(aD[1][2], E1.x, w1); fma2(aD[1][3], E1.y, w1);
            }
            __syncthreads();   // all reads of a1d1 done; shA reused as a2t

            // GELU layer2 + store transposed a2t[col][j] (row stride 196)
            #pragma unroll
            for (int jj = 0; jj < 2; jj++) {
                #pragma unroll
                for (int p = 0; p < 4; p++) {
                    float2 z  = upk2(aA[jj][p]);
                    float2 dz = upk2(aD[jj][p]);
                    float c0 = 0.5f * (1.f + erff(z.x * kSQ));
                    float c1 = 0.5f * (1.f + erff(z.y * kSQ));
                    float a0 = z.x * c0, a1v = z.y * c1;
                    float g0 = c0 + z.x * kPDF * __expf(-0.5f * z.x * z.x);
                    float g1 = c1 + z.y * kPDF * __expf(-0.5f * z.y * z.y);
                    float d0 = g0 * dz.x, d1v = g1 * dz.y;
                    int ca = g * 8 + 2 * p;
                    shA[(ca)     * 196 + j0 + jj] = a0;
                    shA[(ca + 1) * 196 + j0 + jj] = a1v;
                    shA[(16 + ca)     * 196 + j0 + jj] = d0;
                    shA[(16 + ca + 1) * 196 + j0 + jj] = d1v;
                }
            }
            __syncthreads();

            // ---- layer 3: f/Je = [a2;d2] @ W3 (512 outputs) ----
            {
                int col = tid & 31;
                #pragma unroll
                for (int r = 0; r < 3; r++) {
                    int o = r * 192 + tid;
                    if (o < 512) {
                        int dd = o >> 5;
                        const float* ap = shA + col * 196;
                        const float* wp = shW3t + dd * 192;
                        float acc = 0.f;
                        #pragma unroll 8
                        for (int k = 0; k < 192; k += 4) {
                            float4 av = *(const float4*)(ap + k);
                            float4 wv = *(const float4*)(wp + k);
                            acc += av.x * wv.x + av.y * wv.y + av.z * wv.z + av.w * wv.w;
                        }
                        shFJ[col * 17 + dd] = acc;
                    }
                }
            }
            __syncthreads();

            // ---- epilogue: f store / RK4 combine / trace ----
            float wst = (st == 1 || st == 2) ? 3.f : 1.f;
            for (int i = tid; i < 256; i += NTHR) {
                int s = i >> 4, d = i & 15;
                float f = shFJ[s * 17 + d] + shB3[d];
                if (st < 3) shFB[st * 256 + i] = f;
                else shY[i] += dtf * 0.125f *
                     (shFB[i] + 3.f * (shFB[256 + i] + shFB[512 + i]) + f);
            }
            if (tid < 16) {
                int s = tid;
                float tr = 0.f;
                #pragma unroll
                for (int d = 0; d < 16; d++)
                    tr += shYE[d * 36 + 16 + s] * shFJ[(16 + s) * 17 + d];   // e . Je (no bias)
                shTR[s] += wst * tr;
            }
            __syncthreads();
        }
    }

    // logp = -0.5*||z0||^2 - 8*log(2pi) - dlogp ;  dlogp = -dt/8 * sum(w*tr)
    if (tid < 16) {
        int s = tid;
        float ss = 0.f;
        #pragma unroll
        for (int d = 0; d < 16; d++) { float v = shY[s * 16 + d]; ss += v * v; }
        out[s0 + s] = -0.5f * ss - 14.703016531274763f + dtf * 0.125f * shTR[s];
    }
}

extern "C" void kernel_launch(void* const* d_in, const int* in_sizes, int n_in,
                              void* d_out, int out_size) {
    const float* theta = (const float*)d_in[0];
    const float* hg    = (const float*)d_in[1];
    const float* eps   = (const float*)d_in[2];
    const float* W1    = (const float*)d_in[3];
    const float* b1    = (const float*)d_in[4];
    const float* W2    = (const float*)d_in[5];
    const float* b2    = (const float*)d_in[6];
    const float* W3    = (const float*)d_in[7];
    const float* b3    = (const float*)d_in[8];
    float* out = (float*)d_out;

    cudaFuncSetAttribute(ConditionalCNF_27590869910221_kernel,
                         cudaFuncAttributeMaxDynamicSharedMemorySize,
                         SMEM_FLOATS * (int)sizeof(float));
    ConditionalCNF_27590869910221_kernel<<<B_TOT / TM, NTHR,
                                           SMEM_FLOATS * sizeof(float)>>>(
        theta, hg, eps, W1, b1, W2, b2, W3, b3, out);
}

// round 3
// speedup vs baseline: 1.7810x; 1.7810x over previous
#include <cuda_runtime.h>

#define B_TOT   16384
#define TM      16
#define NTHR    384
#define NSTEPS_ 10

typedef unsigned long long u64;

__device__ __forceinline__ u64 pk2(float lo, float hi) {
    u64 r; asm("mov.b64 %0,{%1,%2};" : "=l"(r) : "f"(lo), "f"(hi)); return r;
}
__device__ __forceinline__ float2 upk2(u64 v) {
    float2 f; asm("mov.b64 {%0,%1},%2;" : "=f"(f.x), "=f"(f.y) : "l"(v)); return f;
}
__device__ __forceinline__ void fma2(u64& d, u64 a, u64 b) {
    asm("fma.rn.f32x2 %0,%1,%2,%0;" : "+l"(d) : "l"(a), "l"(b));
}

// Shared layout (floats):
//   [0,36864)      W2s   192x192
//   [36864,43776)  shA   192x36  (aliased: hS 256x16, a2t 32x196)
//   [43776,46848)  shHC  192x16
//   [46848,49920)  shW1a 16x192
//   [49920,50112)  shW1t 192
//   [50112,50304)  shB2  192
//   [50304,53376)  shW3t 16x192
//   [53376,53392)  shB3  16
//   [53392,53968)  shYE  16x36
//   [53968,54512)  shFJ  32x17
//   [54512,55280)  shFB  3x256
//   [55280,55536)  shY   16x16
//   [55536,55552)  shTR  16
#define SMEM_FLOATS 55552

__global__ __launch_bounds__(NTHR, 1)
void ConditionalCNF_27590869910221_kernel(
    const float* __restrict__ theta, const float* __restrict__ hg,
    const float* __restrict__ eps,   const float* __restrict__ W1,
    const float* __restrict__ b1,    const float* __restrict__ W2,
    const float* __restrict__ b2,    const float* __restrict__ W3,
    const float* __restrict__ b3,    float* __restrict__ out)
{
    extern __shared__ float sm[];
    float* shW2  = sm;
    float* shA   = sm + 36864;
    float* shHC  = sm + 43776;
    float* shW1a = sm + 46848;
    float* shW1t = sm + 49920;
    float* shB2  = sm + 50112;
    float* shW3t = sm + 50304;
    float* shB3  = sm + 53376;
    float* shYE  = sm + 53392;
    float* shFJ  = sm + 53968;
    float* shFB  = sm + 54512;
    float* shY   = sm + 55280;
    float* shTR  = sm + 55536;

    const int tid = threadIdx.x;
    const int u = tid % 96;          // column-pair index
    const int q = tid / 96;          // sample quarter (0..3)
    const int j0 = 2 * u;
    const int sb = 4 * q;            // sample base within tile
    const int s0 = blockIdx.x * TM;
    const float dtf = -0.1f;

    // ---------------- phase 0: stage weights / state ----------------
    {
        const float4* W2g4 = (const float4*)W2;
        float4* shW24 = (float4*)shW2;
        for (int i = tid; i < 36864 / 4; i += NTHR) shW24[i] = W2g4[i];
        for (int i = tid; i < 3072; i += NTHR) shW1a[i] = W1[i];           // rows 0..15
        for (int i = tid; i < 192; i += NTHR) {
            shW1t[i] = W1[272 * 192 + i];                                  // t row
            shB2[i]  = b2[i];
        }
        for (int i = tid; i < 3072; i += NTHR) {                           // W3 transpose
            int k = i >> 4, dd = i & 15;
            shW3t[dd * 192 + k] = W3[i];
        }
        if (tid < 16) { shB3[tid] = b3[tid]; shTR[tid] = 0.f; }
        for (int i = tid; i < 256; i += NTHR) shY[i] = theta[s0 * 16 + i];
        // h tile into shA as hS[c][s], row stride 16
        const float4* hg4 = (const float4*)hg;
        for (int i = tid; i < 1024; i += NTHR) {
            float4 v = hg4[s0 * 64 + i];
            int s = i >> 6, c = (i & 63) * 4;
            shA[(c + 0) * 16 + s] = v.x; shA[(c + 1) * 16 + s] = v.y;
            shA[(c + 2) * 16 + s] = v.z; shA[(c + 3) * 16 + s] = v.w;
        }
    }
    __syncthreads();

    // ---------------- hc = b1 + h @ W1[16:272,:] ----------------
    {
        u64 acc[2][2];
        float bj0 = b1[j0], bj1 = b1[j0 + 1];
        acc[0][0] = acc[0][1] = pk2(bj0, bj0);
        acc[1][0] = acc[1][1] = pk2(bj1, bj1);
        const float* hrow = shA + sb;
        #pragma unroll 4
        for (int k = 0; k < 256; k++) {
            float2 w = *(const float2*)(W1 + (16 + k) * 192 + j0);         // L2-resident
            u64 w0 = pk2(w.x, w.x), w1 = pk2(w.y, w.y);
            ulonglong2 A0 = *(const ulonglong2*)(hrow + k * 16);
            fma2(acc[0][0], A0.x, w0); fma2(acc[0][1], A0.y, w0);
            fma2(acc[1][0], A0.x, w1); fma2(acc[1][1], A0.y, w1);
        }
        #pragma unroll
        for (int jj = 0; jj < 2; jj++)
            #pragma unroll
            for (int p = 0; p < 2; p++) {
                float2 v = upk2(acc[jj][p]);
                shHC[(j0 + jj) * 16 + sb + 2 * p]     = v.x;
                shHC[(j0 + jj) * 16 + sb + 2 * p + 1] = v.y;
            }
    }
    __syncthreads();

    const float kSQ = 0.70710678118654752f;    // 1/sqrt(2)
    const float kPDF = 0.3989422804014327f;    // 1/sqrt(2*pi)

    u64 aA[2][2], aD[2][2];

    for (int step = 0; step < NSTEPS_; step++) {
        float t0 = 1.0f + dtf * (float)step;
        for (int st = 0; st < 4; st++) {
            float tc = t0 + dtf * (st == 0 ? 0.f : st == 1 ? (1.f / 3.f)
                                 : st == 2 ? (2.f / 3.f) : 1.f);

            // ---- phase A: stage y + eps into shYE ----
            if (tid < 256) {
                int i = tid;
                int s = i >> 4, d = i & 15;
                float e = eps[(((step * 4 + st) * B_TOT) + s0 + s) * 16 + d];
                shYE[d * 36 + 16 + s] = e;
                float yb = shY[i];
                float yc;
                if      (st == 0) yc = yb;
                else if (st == 1) yc = yb + (dtf * (1.f / 3.f)) * shFB[i];
                else if (st == 2) yc = yb + dtf * (shFB[256 + i] - (1.f / 3.f) * shFB[i]);
                else              yc = yb + dtf * (shFB[i] - shFB[256 + i] + shFB[512 + i]);
                shYE[d * 36 + s] = yc;
            }
            __syncthreads();

            // ---- layer 1: z1 = hc + t*W1t + y@W1a ; dz1 = e@W1a ----
            #pragma unroll
            for (int jj = 0; jj < 2; jj++) {
                float tw = tc * shW1t[j0 + jj];
                const float* hcp = shHC + (j0 + jj) * 16 + sb;
                #pragma unroll
                for (int p = 0; p < 2; p++) {
                    aA[jj][p] = pk2(hcp[2 * p] + tw, hcp[2 * p + 1] + tw);
                    aD[jj][p] = 0ull;
                }
            }
            #pragma unroll
            for (int k = 0; k < 16; k++) {
                const float* ar = shYE + k * 36 + sb;
                ulonglong2 A0 = *(const ulonglong2*)ar;
                ulonglong2 E0 = *(const ulonglong2*)(ar + 16);
                float2 w = *(const float2*)(shW1a + k * 192 + j0);
                u64 w0 = pk2(w.x, w.x), w1 = pk2(w.y, w.y);
                fma2(aA[0][0], A0.x, w0); fma2(aA[0][1], A0.y, w0);
                fma2(aA[1][0], A0.x, w1); fma2(aA[1][1], A0.y, w1);
                fma2(aD[0][0], E0.x, w0); fma2(aD[0][1], E0.y, w0);
                fma2(aD[1][0], E0.x, w1); fma2(aD[1][1], E0.y, w1);
            }

            // GELU layer1 + store a1/d1 rows
            #pragma unroll
            for (int jj = 0; jj < 2; jj++) {
                float va[4], vd[4];
                #pragma unroll
                for (int p = 0; p < 2; p++) {
                    float2 z  = upk2(aA[jj][p]);
                    float2 dz = upk2(aD[jj][p]);
                    float c0 = 0.5f * (1.f + erff(z.x * kSQ));
                    float c1 = 0.5f * (1.f + erff(z.y * kSQ));
                    va[2 * p]     = z.x * c0;
                    va[2 * p + 1] = z.y * c1;
                    float g0 = c0 + z.x * kPDF * __expf(-0.5f * z.x * z.x);
                    float g1 = c1 + z.y * kPDF * __expf(-0.5f * z.y * z.y);
                    vd[2 * p]     = g0 * dz.x;
                    vd[2 * p + 1] = g1 * dz.y;
                }
                float* row = shA + (j0 + jj) * 36 + sb;
                *(float4*)(row)      = make_float4(va[0], va[1], va[2], va[3]);
                *(float4*)(row + 16) = make_float4(vd[0], vd[1], vd[2], vd[3]);
            }
            __syncthreads();

            // ---- layer 2: z2 = a1@W2 + b2 ; dz2 = d1@W2 ----
            #pragma unroll
            for (int jj = 0; jj < 2; jj++) {
                float bb = shB2[j0 + jj];
                u64 bp = pk2(bb, bb);
                #pragma unroll
                for (int p = 0; p < 2; p++) { aA[jj][p] = bp; aD[jj][p] = 0ull; }
            }
            #pragma unroll 8
            for (int k = 0; k < 192; k++) {
                const float* ar = shA + k * 36 + sb;
                ulonglong2 A0 = *(const ulonglong2*)ar;
                ulonglong2 E0 = *(const ulonglong2*)(ar + 16);
                float2 w = *(const float2*)(shW2 + k * 192 + j0);
                u64 w0 = pk2(w.x, w.x), w1 = pk2(w.y, w.y);
                fma2(aA[0][0], A0.x, w0); fma2(aA[0][1], A0.y, w0);
                fma2(aA[1][0], A0.x, w1); fma2(aA[1][1], A0.y, w1);
                fma2(aD[0][0], E0.x, w0); fma2(aD[0][1], E0.y, w0);
                fma2(aD[1][0], E0.x, w1); fma2(aD[1][1], E0.y, w1);
            }
            __syncthreads();   // all reads of a1d1 done; shA reused as a2t

            // GELU layer2 + store transposed a2t[col][j] (row stride 196)
            #pragma unroll
            for (int jj = 0; jj < 2; jj++) {
                #pragma unroll
                for (int p = 0; p < 2; p++) {
                    float2 z  = upk2(aA[jj][p]);
                    float2 dz = upk2(aD[jj][p]);
                    float c0 = 0.5f * (1.f + erff(z.x * kSQ));
                    float c1 = 0.5f * (1.f + erff(z.y * kSQ));
                    float a0 = z.x * c0, a1v = z.y * c1;
                    float g0 = c0 + z.x * kPDF * __expf(-0.5f * z.x * z.x);
                    float g1 = c1 + z.y * kPDF * __expf(-0.5f * z.y * z.y);
                    float d0 = g0 * dz.x, d1v = g1 * dz.y;
                    int ca = sb + 2 * p;
                    shA[(ca)     * 196 + j0 + jj] = a0;
                    shA[(ca + 1) * 196 + j0 + jj] = a1v;
                    shA[(16 + ca)     * 196 + j0 + jj] = d0;
                    shA[(16 + ca + 1) * 196 + j0 + jj] = d1v;
                }
            }
            __syncthreads();

            // ---- layer 3: f/Je = [a2;d2] @ W3 (512 outputs) ----
            {
                int col = tid & 31;
                #pragma unroll
                for (int r = 0; r < 2; r++) {
                    int o = r * NTHR + tid;
                    if (o < 512) {
                        int dd = o >> 5;
                        const float* ap = shA + col * 196;
                        const float* wp = shW3t + dd * 192;
                        float acc = 0.f;
                        #pragma unroll 8
                        for (int k = 0; k < 192; k += 4) {
                            float4 av = *(const float4*)(ap + k);
                            float4 wv = *(const float4*)(wp + k);
                            acc += av.x * wv.x + av.y * wv.y + av.z * wv.z + av.w * wv.w;
                        }
                        shFJ[col * 17 + dd] = acc;
                    }
                }
            }
            __syncthreads();

            // ---- epilogue: f store / RK4 combine / trace ----
            float wst = (st == 1 || st == 2) ? 3.f : 1.f;
            if (tid < 256) {
                int i = tid;
                int s = i >> 4, d = i & 15;
                float f = shFJ[s * 17 + d] + shB3[d];
                if (st < 3) shFB[st * 256 + i] = f;
                else shY[i] += dtf * 0.125f *
                     (shFB[i] + 3.f * (shFB[256 + i] + shFB[512 + i]) + f);
            }
            if (tid < 16) {
                int s = tid;
                float tr = 0.f;
                #pragma unroll
                for (int d = 0; d < 16; d++)
                    tr += shYE[d * 36 + 16 + s] * shFJ[(16 + s) * 17 + d];   // e . Je (no bias)
                shTR[s] += wst * tr;
            }
            __syncthreads();
        }
    }

    // logp = -0.5*||z0||^2 - 8*log(2pi) - dlogp ;  dlogp = -dt/8 * sum(w*tr)
    if (tid < 16) {
        int s = tid;
        float ss = 0.f;
        #pragma unroll
        for (int d = 0; d < 16; d++) { float v = shY[s * 16 + d]; ss += v * v; }
        out[s0 + s] = -0.5f * ss - 14.703016531274763f + dtf * 0.125f * shTR[s];
    }
}

extern "C" void kernel_launch(void* const* d_in, const int* in_sizes, int n_in,
                              void* d_out, int out_size) {
    const float* theta = (const float*)d_in[0];
    const float* hg    = (const float*)d_in[1];
    const float* eps   = (const float*)d_in[2];
    const float* W1    = (const float*)d_in[3];
    const float* b1    = (const float*)d_in[4];
    const float* W2    = (const float*)d_in[5];
    const float* b2    = (const float*)d_in[6];
    const float* W3    = (const float*)d_in[7];
    const float* b3    = (const float*)d_in[8];
    float* out = (float*)d_out;

    cudaFuncSetAttribute(ConditionalCNF_27590869910221_kernel,
                         cudaFuncAttributeMaxDynamicSharedMemorySize,
                         SMEM_FLOATS * (int)sizeof(float));
    ConditionalCNF_27590869910221_kernel<<<B_TOT / TM, NTHR,
                                           SMEM_FLOATS * sizeof(float)>>>(
        theta, hg, eps, W1, b1, W2, b2, W3, b3, out);
}

// round 5
// speedup vs baseline: 1.8918x; 1.0622x over previous
#include <cuda_runtime.h>

#define B_TOT   16384
#define TM      16
#define NTHR    384
#define NSTEPS_ 10

typedef unsigned long long u64;

__device__ __forceinline__ u64 pk2(float lo, float hi) {
    u64 r; asm("mov.b64 %0,{%1,%2};" : "=l"(r) : "f"(lo), "f"(hi)); return r;
}
__device__ __forceinline__ float2 upk2(u64 v) {
    float2 f; asm("mov.b64 {%0,%1},%2;" : "=f"(f.x), "=f"(f.y) : "l"(v)); return f;
}
__device__ __forceinline__ void fma2(u64& d, u64 a, u64 b) {
    asm("fma.rn.f32x2 %0,%1,%2,%0;" : "+l"(d) : "l"(a), "l"(b));
}

// Shared layout (floats):
//   [0,36864)      W2s   192x192
//   [36864,43776)  shA   192x36  (aliased: hS 256x16, a2t 16x196)
//   [43776,46848)  shHC  192x16
//   [46848,49920)  shW1a 16x192
//   [49920,50112)  shW1t 192
//   [50112,50304)  shB2  192
//   [50304,53376)  shW3t 16x192
//   [53376,53392)  shB3  16
//   [53392,53968)  shYE  16x36
//   [53968,54512)  shFJ  16x17 (in 544 slot)
//   [54512,55280)  shFB  3x256
//   [55280,55536)  shY   16x16
//   [55536,55552)  shTR  16
//   [55552,55600)  shTW  12x4 warp trace partials
#define SMEM_FLOATS 55600

__global__ __launch_bounds__(NTHR, 1)
void ConditionalCNF_27590869910221_kernel(
    const float* __restrict__ theta, const float* __restrict__ hg,
    const float* __restrict__ eps,   const float* __restrict__ W1,
    const float* __restrict__ b1,    const float* __restrict__ W2,
    const float* __restrict__ b2,    const float* __restrict__ W3,
    const float* __restrict__ b3,    float* __restrict__ out)
{
    extern __shared__ float sm[];
    float* shW2  = sm;
    float* shA   = sm + 36864;
    float* shHC  = sm + 43776;
    float* shW1a = sm + 46848;
    float* shW1t = sm + 49920;
    float* shB2  = sm + 50112;
    float* shW3t = sm + 50304;
    float* shB3  = sm + 53376;
    float* shYE  = sm + 53392;
    float* shFJ  = sm + 53968;
    float* shFB  = sm + 54512;
    float* shY   = sm + 55280;
    float* shTR  = sm + 55536;
    float* shTW  = sm + 55552;

    const int tid = threadIdx.x;
    const int u = tid % 96;          // column-pair index
    const int q = tid / 96;          // sample quarter (0..3)
    const int wid = tid >> 5;        // warp id (uniform q per warp)
    const int lane = tid & 31;
    const int j0 = 2 * u;
    const int sb = 4 * q;            // sample base within tile
    const int s0 = blockIdx.x * TM;
    const float dtf = -0.1f;

    // ---------------- phase 0: stage weights / state ----------------
    {
        const float4* W2g4 = (const float4*)W2;
        float4* shW24 = (float4*)shW2;
        for (int i = tid; i < 36864 / 4; i += NTHR) shW24[i] = W2g4[i];
        for (int i = tid; i < 3072; i += NTHR) shW1a[i] = W1[i];           // rows 0..15
        for (int i = tid; i < 192; i += NTHR) {
            shW1t[i] = W1[272 * 192 + i];                                  // t row
            shB2[i]  = b2[i];
        }
        for (int i = tid; i < 3072; i += NTHR) {                           // W3 transpose
            int k = i >> 4, dd = i & 15;
            shW3t[dd * 192 + k] = W3[i];
        }
        if (tid < 16) { shB3[tid] = b3[tid]; shTR[tid] = 0.f; }
        for (int i = tid; i < 256; i += NTHR) shY[i] = theta[s0 * 16 + i];
        // h tile into shA as hS[c][s], row stride 16
        const float4* hg4 = (const float4*)hg;
        for (int i = tid; i < 1024; i += NTHR) {
            float4 v = hg4[s0 * 64 + i];
            int s = i >> 6, c = (i & 63) * 4;
            shA[(c + 0) * 16 + s] = v.x; shA[(c + 1) * 16 + s] = v.y;
            shA[(c + 2) * 16 + s] = v.z; shA[(c + 3) * 16 + s] = v.w;
        }
    }
    __syncthreads();

    // ---------------- hc = b1 + h @ W1[16:272,:] ----------------
    {
        u64 acc[2][2];
        float bj0 = b1[j0], bj1 = b1[j0 + 1];
        acc[0][0] = acc[0][1] = pk2(bj0, bj0);
        acc[1][0] = acc[1][1] = pk2(bj1, bj1);
        const float* hrow = shA + sb;
        #pragma unroll 4
        for (int k = 0; k < 256; k++) {
            float2 w = *(const float2*)(W1 + (16 + k) * 192 + j0);         // L2-resident
            u64 w0 = pk2(w.x, w.x), w1 = pk2(w.y, w.y);
            ulonglong2 A0 = *(const ulonglong2*)(hrow + k * 16);
            fma2(acc[0][0], A0.x, w0); fma2(acc[0][1], A0.y, w0);
            fma2(acc[1][0], A0.x, w1); fma2(acc[1][1], A0.y, w1);
        }
        #pragma unroll
        for (int jj = 0; jj < 2; jj++)
            #pragma unroll
            for (int p = 0; p < 2; p++) {
                float2 v = upk2(acc[jj][p]);
                shHC[(j0 + jj) * 16 + sb + 2 * p]     = v.x;
                shHC[(j0 + jj) * 16 + sb + 2 * p + 1] = v.y;
            }
    }
    __syncthreads();

    const float kSQ = 0.70710678118654752f;    // 1/sqrt(2)
    const float kPDF = 0.3989422804014327f;    // 1/sqrt(2*pi)

    u64 aA[2][2], aD[2][2], aW[2][2];

    // eps prefetch: each of first 256 threads owns one (s,d) slot of the tile
    float epsReg = 0.f;
    const int es = tid >> 4, ed = tid & 15;
    if (tid < 256) epsReg = eps[((0 * B_TOT) + s0 + es) * 16 + ed];

    for (int step = 0; step < NSTEPS_; step++) {
        float t0 = 1.0f + dtf * (float)step;
        for (int st = 0; st < 4; st++) {
            int idx = step * 4 + st;
            float tc = t0 + dtf * (st == 0 ? 0.f : st == 1 ? (1.f / 3.f)
                                 : st == 2 ? (2.f / 3.f) : 1.f);

            // ---- phase A: stage y + eps into shYE (eps from prefetch reg) ----
            if (tid < 256) {
                int i = tid;
                int s = es, d = ed;
                shYE[d * 36 + 16 + s] = epsReg;
                float yb = shY[i];
                float yc;
                if      (st == 0) yc = yb;
                else if (st == 1) yc = yb + (dtf * (1.f / 3.f)) * shFB[i];
                else if (st == 2) yc = yb + dtf * (shFB[256 + i] - (1.f / 3.f) * shFB[i]);
                else              yc = yb + dtf * (shFB[i] - shFB[256 + i] + shFB[512 + i]);
                shYE[d * 36 + s] = yc;
                int nxt = idx + 1; if (nxt > 39) nxt = 39;
                epsReg = eps[((nxt * B_TOT) + s0 + s) * 16 + d];           // prefetch next stage
            }
            __syncthreads();

            // ---- layer 1: z1 = hc + t*W1t + y@W1a ; dz1 = e@W1a ; we = W3.e ----
            #pragma unroll
            for (int jj = 0; jj < 2; jj++) {
                float tw = tc * shW1t[j0 + jj];
                const float* hcp = shHC + (j0 + jj) * 16 + sb;
                #pragma unroll
                for (int p = 0; p < 2; p++) {
                    aA[jj][p] = pk2(hcp[2 * p] + tw, hcp[2 * p + 1] + tw);
                    aD[jj][p] = 0ull;
                    aW[jj][p] = 0ull;
                }
            }
            #pragma unroll
            for (int k = 0; k < 16; k++) {
                const float* ar = shYE + k * 36 + sb;
                ulonglong2 A0 = *(const ulonglong2*)ar;
                ulonglong2 E0 = *(const ulonglong2*)(ar + 16);
                float2 w = *(const float2*)(shW1a + k * 192 + j0);
                float2 w3 = *(const float2*)(shW3t + k * 192 + j0);        // W3[j][k-dim d]
                u64 w0 = pk2(w.x, w.x), w1 = pk2(w.y, w.y);
                u64 v0 = pk2(w3.x, w3.x), v1 = pk2(w3.y, w3.y);
                fma2(aA[0][0], A0.x, w0); fma2(aA[0][1], A0.y, w0);
                fma2(aA[1][0], A0.x, w1); fma2(aA[1][1], A0.y, w1);
                fma2(aD[0][0], E0.x, w0); fma2(aD[0][1], E0.y, w0);
                fma2(aD[1][0], E0.x, w1); fma2(aD[1][1], E0.y, w1);
                fma2(aW[0][0], E0.x, v0); fma2(aW[0][1], E0.y, v0);
                fma2(aW[1][0], E0.x, v1); fma2(aW[1][1], E0.y, v1);
            }

            // GELU layer1 + store a1/d1 rows
            #pragma unroll
            for (int jj = 0; jj < 2; jj++) {
                float va[4], vd[4];
                #pragma unroll
                for (int p = 0; p < 2; p++) {
                    float2 z  = upk2(aA[jj][p]);
                    float2 dz = upk2(aD[jj][p]);
                    float c0 = 0.5f * (1.f + erff(z.x * kSQ));
                    float c1 = 0.5f * (1.f + erff(z.y * kSQ));
                    va[2 * p]     = z.x * c0;
                    va[2 * p + 1] = z.y * c1;
                    float g0 = c0 + z.x * kPDF * __expf(-0.5f * z.x * z.x);
                    float g1 = c1 + z.y * kPDF * __expf(-0.5f * z.y * z.y);
                    vd[2 * p]     = g0 * dz.x;
                    vd[2 * p + 1] = g1 * dz.y;
                }
                float* row = shA + (j0 + jj) * 36 + sb;
                *(float4*)(row)      = make_float4(va[0], va[1], va[2], va[3]);
                *(float4*)(row + 16) = make_float4(vd[0], vd[1], vd[2], vd[3]);
            }
            __syncthreads();

            // ---- layer 2: z2 = a1@W2 + b2 ; dz2 = d1@W2 ----
            #pragma unroll
            for (int jj = 0; jj < 2; jj++) {
                float bb = shB2[j0 + jj];
                u64 bp = pk2(bb, bb);
                #pragma unroll
                for (int p = 0; p < 2; p++) { aA[jj][p] = bp; aD[jj][p] = 0ull; }
            }
            #pragma unroll 8
            for (int k = 0; k < 192; k++) {
                const float* ar = shA + k * 36 + sb;
                ulonglong2 A0 = *(const ulonglong2*)ar;
                ulonglong2 E0 = *(const ulonglong2*)(ar + 16);
                float2 w = *(const float2*)(shW2 + k * 192 + j0);
                u64 w0 = pk2(w.x, w.x), w1 = pk2(w.y, w.y);
                fma2(aA[0][0], A0.x, w0); fma2(aA[0][1], A0.y, w0);
                fma2(aA[1][0], A0.x, w1); fma2(aA[1][1], A0.y, w1);
                fma2(aD[0][0], E0.x, w0); fma2(aD[0][1], E0.y, w0);
                fma2(aD[1][0], E0.x, w1); fma2(aD[1][1], E0.y, w1);
            }
            __syncthreads();   // all reads of a1d1 done; shA reused as a2t

            // GELU layer2: store a2 transposed; trace partial from d2 in regs
            float tp[4] = {0.f, 0.f, 0.f, 0.f};
            #pragma unroll
            for (int jj = 0; jj < 2; jj++) {
                #pragma unroll
                for (int p = 0; p < 2; p++) {
                    float2 z  = upk2(aA[jj][p]);
                    float2 dz = upk2(aD[jj][p]);
                    float c0 = 0.5f * (1.f + erff(z.x * kSQ));
                    float c1 = 0.5f * (1.f + erff(z.y * kSQ));
                    float a0 = z.x * c0, a1v = z.y * c1;
                    float g0 = c0 + z.x * kPDF * __expf(-0.5f * z.x * z.x);
                    float g1 = c1 + z.y * kPDF * __expf(-0.5f * z.y * z.y);
                    float d0 = g0 * dz.x, d1v = g1 * dz.y;
                    int ca = sb + 2 * p;
                    shA[(ca)     * 196 + j0 + jj] = a0;
                    shA[(ca + 1) * 196 + j0 + jj] = a1v;
                    float2 wv = upk2(aW[jj][p]);
                    tp[2 * p]     += d0  * wv.x;      // d2 . (W3 e)
                    tp[2 * p + 1] += d1v * wv.y;
                }
            }
            // warp butterfly reduce the 4 sample-partials (warp uniform in q)
            #pragma unroll
            for (int off = 16; off > 0; off >>= 1) {
                #pragma unroll
                for (int i = 0; i < 4; i++)
                    tp[i] += __shfl_xor_sync(0xFFFFFFFFu, tp[i], off);
            }
            if (lane == 0) {
                #pragma unroll
                for (int i = 0; i < 4; i++) shTW[wid * 4 + i] = tp[i];
            }
            __syncthreads();

            // ---- layer 3 (a-path only): f = a2 @ W3 (256 outputs) ----
            if (tid < 256) {
                int s = tid & 15, dd = tid >> 4;
                const float* ap = shA + s * 196;
                const float* wp = shW3t + dd * 192;
                float acc = 0.f;
                #pragma unroll 8
                for (int k = 0; k < 192; k += 4) {
                    float4 av = *(const float4*)(ap + k);
                    float4 wv = *(const float4*)(wp + k);
                    acc += av.x * wv.x + av.y * wv.y + av.z * wv.z + av.w * wv.w;
                }
                shFJ[s * 17 + dd] = acc;
            }
            __syncthreads();

            // ---- epilogue: f store / RK4 combine / trace accumulate ----
            float wst = (st == 1 || st == 2) ? 3.f : 1.f;
            if (tid < 256) {
                int i = tid;
                int s = es, d = ed;
                float f = shFJ[s * 17 + d] + shB3[d];
                if (st < 3) shFB[st * 256 + i] = f;
                else shY[i] += dtf * 0.125f *
                     (shFB[i] + 3.f * (shFB[256 + i] + shFB[512 + i]) + f);
            }
            if (tid < 16) {
                int s = tid;
                int qq = s >> 2, si = s & 3;
                float tr = shTW[(3 * qq) * 4 + si] + shTW[(3 * qq + 1) * 4 + si]
                         + shTW[(3 * qq + 2) * 4 + si];
                shTR[s] += wst * tr;
            }
            __syncthreads();
        }
    }

    // logp = -0.5*||z0||^2 - 8*log(2pi) - dlogp ;  dlogp = -dt/8 * sum(w*tr)
    if (tid < 16) {
        int s = tid;
        float ss = 0.f;
        #pragma unroll
        for (int d = 0; d < 16; d++) { float v = shY[s * 16 + d]; ss += v * v; }
        out[s0 + s] = -0.5f * ss - 14.703016531274763f + dtf * 0.125f * shTR[s];
    }
}

extern "C" void kernel_launch(void* const* d_in, const int* in_sizes, int n_in,
                              void* d_out, int out_size) {
    const float* theta = (const float*)d_in[0];
    const float* hg    = (const float*)d_in[1];
    const float* eps   = (const float*)d_in[2];
    const float* W1    = (const float*)d_in[3];
    const float* b1    = (const float*)d_in[4];
    const float* W2    = (const float*)d_in[5];
    const float* b2    = (const float*)d_in[6];
    const float* W3    = (const float*)d_in[7];
    const float* b3    = (const float*)d_in[8];
    float* out = (float*)d_out;

    cudaFuncSetAttribute(ConditionalCNF_27590869910221_kernel,
                         cudaFuncAttributeMaxDynamicSharedMemorySize,
                         SMEM_FLOATS * (int)sizeof(float));
    ConditionalCNF_27590869910221_kernel<<<B_TOT / TM, NTHR,
                                           SMEM_FLOATS * sizeof(float)>>>(
        theta, hg, eps, W1, b1, W2, b2, W3, b3, out);
}

// round 6
// speedup vs baseline: 1.8935x; 1.0009x over previous
#include <cuda_runtime.h>

#define B_TOT   16384
#define TM      16
#define NTHR    384
#define NSTEPS_ 10

typedef unsigned long long u64;

__device__ __forceinline__ u64 pk2(float lo, float hi) {
    u64 r; asm("mov.b64 %0,{%1,%2};" : "=l"(r) : "f"(lo), "f"(hi)); return r;
}
__device__ __forceinline__ float2 upk2(u64 v) {
    float2 f; asm("mov.b64 {%0,%1},%2;" : "=f"(f.x), "=f"(f.y) : "l"(v)); return f;
}
__device__ __forceinline__ void fma2(u64& d, u64 a, u64 b) {
    asm("fma.rn.f32x2 %0,%1,%2,%0;" : "+l"(d) : "l"(a), "l"(b));
}

// Shared layout (floats):
//   [0,36864)      W2s   192x192
//   [36864,43776)  shA   192x36  (aliased: hS 256x16, a2t 16x196)
//   [43776,46848)  shHC  192x16
//   [46848,49920)  shW1a 16x192
//   [49920,50112)  shW1t 192
//   [50112,50304)  shB2  192
//   [50304,53376)  shW3t 16x192
//   [53376,53392)  shB3  16
//   [53392,53968)  shYE  16x36
//   [53968,54512)  shFJ  16x17 (in 544 slot)
//   [54512,55280)  shFB  3x256
//   [55280,55536)  shY   16x16
//   [55536,55552)  shTR  16
//   [55552,55600)  shTW  12x4 warp trace partials
#define SMEM_FLOATS 55600

__global__ __launch_bounds__(NTHR, 1)
void ConditionalCNF_27590869910221_kernel(
    const float* __restrict__ theta, const float* __restrict__ hg,
    const float* __restrict__ eps,   const float* __restrict__ W1,
    const float* __restrict__ b1,    const float* __restrict__ W2,
    const float* __restrict__ b2,    const float* __restrict__ W3,
    const float* __restrict__ b3,    float* __restrict__ out)
{
    extern __shared__ float sm[];
    float* shW2  = sm;
    float* shA   = sm + 36864;
    float* shHC  = sm + 43776;
    float* shW1a = sm + 46848;
    float* shW1t = sm + 49920;
    float* shB2  = sm + 50112;
    float* shW3t = sm + 50304;
    float* shB3  = sm + 53376;
    float* shYE  = sm + 53392;
    float* shFJ  = sm + 53968;
    float* shFB  = sm + 54512;
    float* shY   = sm + 55280;
    float* shTR  = sm + 55536;
    float* shTW  = sm + 55552;

    const int tid = threadIdx.x;
    const int u = tid % 96;          // column-pair index
    const int q = tid / 96;          // sample quarter (0..3)
    const int wid = tid >> 5;        // warp id (uniform q per warp)
    const int lane = tid & 31;
    const int j0 = 2 * u;
    const int sb = 4 * q;            // sample base within tile
    const int s0 = blockIdx.x * TM;
    const float dtf = -0.1f;

    // ---------------- phase 0: stage weights / state ----------------
    {
        const float4* W2g4 = (const float4*)W2;
        float4* shW24 = (float4*)shW2;
        for (int i = tid; i < 36864 / 4; i += NTHR) shW24[i] = W2g4[i];
        for (int i = tid; i < 3072; i += NTHR) shW1a[i] = W1[i];           // rows 0..15
        for (int i = tid; i < 192; i += NTHR) {
            shW1t[i] = W1[272 * 192 + i];                                  // t row
            shB2[i]  = b2[i];
        }
        for (int i = tid; i < 3072; i += NTHR) {                           // W3 transpose
            int k = i >> 4, dd = i & 15;
            shW3t[dd * 192 + k] = W3[i];
        }
        if (tid < 16) { shB3[tid] = b3[tid]; shTR[tid] = 0.f; }
        for (int i = tid; i < 256; i += NTHR) shY[i] = theta[s0 * 16 + i];
        // h tile into shA as hS[c][s], row stride 16
        const float4* hg4 = (const float4*)hg;
        for (int i = tid; i < 1024; i += NTHR) {
            float4 v = hg4[s0 * 64 + i];
            int s = i >> 6, c = (i & 63) * 4;
            shA[(c + 0) * 16 + s] = v.x; shA[(c + 1) * 16 + s] = v.y;
            shA[(c + 2) * 16 + s] = v.z; shA[(c + 3) * 16 + s] = v.w;
        }
    }
    __syncthreads();

    // ---------------- hc = b1 + h @ W1[16:272,:] ----------------
    {
        u64 acc[2][2];
        float bj0 = b1[j0], bj1 = b1[j0 + 1];
        acc[0][0] = acc[0][1] = pk2(bj0, bj0);
        acc[1][0] = acc[1][1] = pk2(bj1, bj1);
        const float* hrow = shA + sb;
        #pragma unroll 4
        for (int k = 0; k < 256; k++) {
            float2 w = *(const float2*)(W1 + (16 + k) * 192 + j0);         // L2-resident
            u64 w0 = pk2(w.x, w.x), w1 = pk2(w.y, w.y);
            ulonglong2 A0 = *(const ulonglong2*)(hrow + k * 16);
            fma2(acc[0][0], A0.x, w0); fma2(acc[0][1], A0.y, w0);
            fma2(acc[1][0], A0.x, w1); fma2(acc[1][1], A0.y, w1);
        }
        #pragma unroll
        for (int jj = 0; jj < 2; jj++)
            #pragma unroll
            for (int p = 0; p < 2; p++) {
                float2 v = upk2(acc[jj][p]);
                shHC[(j0 + jj) * 16 + sb + 2 * p]     = v.x;
                shHC[(j0 + jj) * 16 + sb + 2 * p + 1] = v.y;
            }
    }
    __syncthreads();

    const float kSQ = 0.70710678118654752f;    // 1/sqrt(2)
    const float kPDF = 0.3989422804014327f;    // 1/sqrt(2*pi)

    u64 aA[2][2], aD[2][2], aW[2][2];

    // eps prefetch: each of first 256 threads owns one (s,d) slot of the tile
    float epsReg = 0.f;
    const int es = tid >> 4, ed = tid & 15;
    if (tid < 256) epsReg = eps[((0 * B_TOT) + s0 + es) * 16 + ed];

    for (int step = 0; step < NSTEPS_; step++) {
        float t0 = 1.0f + dtf * (float)step;
        for (int st = 0; st < 4; st++) {
            int idx = step * 4 + st;
            float tc = t0 + dtf * (st == 0 ? 0.f : st == 1 ? (1.f / 3.f)
                                 : st == 2 ? (2.f / 3.f) : 1.f);

            // ---- phase A: stage y + eps into shYE (eps from prefetch reg) ----
            if (tid < 256) {
                int i = tid;
                int s = es, d = ed;
                shYE[d * 36 + 16 + s] = epsReg;
                float yb = shY[i];
                float yc;
                if      (st == 0) yc = yb;
                else if (st == 1) yc = yb + (dtf * (1.f / 3.f)) * shFB[i];
                else if (st == 2) yc = yb + dtf * (shFB[256 + i] - (1.f / 3.f) * shFB[i]);
                else              yc = yb + dtf * (shFB[i] - shFB[256 + i] + shFB[512 + i]);
                shYE[d * 36 + s] = yc;
                int nxt = idx + 1; if (nxt > 39) nxt = 39;
                epsReg = eps[((nxt * B_TOT) + s0 + s) * 16 + d];           // prefetch next stage
            }
            __syncthreads();

            // ---- layer 1: z1 = hc + t*W1t + y@W1a ; dz1 = e@W1a ; we = W3.e ----
            #pragma unroll
            for (int jj = 0; jj < 2; jj++) {
                float tw = tc * shW1t[j0 + jj];
                const float* hcp = shHC + (j0 + jj) * 16 + sb;
                #pragma unroll
                for (int p = 0; p < 2; p++) {
                    aA[jj][p] = pk2(hcp[2 * p] + tw, hcp[2 * p + 1] + tw);
                    aD[jj][p] = 0ull;
                    aW[jj][p] = 0ull;
                }
            }
            #pragma unroll
            for (int k = 0; k < 16; k++) {
                const float* ar = shYE + k * 36 + sb;
                ulonglong2 A0 = *(const ulonglong2*)ar;
                ulonglong2 E0 = *(const ulonglong2*)(ar + 16);
                float2 w = *(const float2*)(shW1a + k * 192 + j0);
                float2 w3 = *(const float2*)(shW3t + k * 192 + j0);        // W3[j][k-dim d]
                u64 w0 = pk2(w.x, w.x), w1 = pk2(w.y, w.y);
                u64 v0 = pk2(w3.x, w3.x), v1 = pk2(w3.y, w3.y);
                fma2(aA[0][0], A0.x, w0); fma2(aA[0][1], A0.y, w0);
                fma2(aA[1][0], A0.x, w1); fma2(aA[1][1], A0.y, w1);
                fma2(aD[0][0], E0.x, w0); fma2(aD[0][1], E0.y, w0);
                fma2(aD[1][0], E0.x, w1); fma2(aD[1][1], E0.y, w1);
                fma2(aW[0][0], E0.x, v0); fma2(aW[0][1], E0.y, v0);
                fma2(aW[1][0], E0.x, v1); fma2(aW[1][1], E0.y, v1);
            }

            // GELU layer1 + store a1/d1 rows
            #pragma unroll
            for (int jj = 0; jj < 2; jj++) {
                float va[4], vd[4];
                #pragma unroll
                for (int p = 0; p < 2; p++) {
                    float2 z  = upk2(aA[jj][p]);
                    float2 dz = upk2(aD[jj][p]);
                    float c0 = 0.5f * (1.f + erff(z.x * kSQ));
                    float c1 = 0.5f * (1.f + erff(z.y * kSQ));
                    va[2 * p]     = z.x * c0;
                    va[2 * p + 1] = z.y * c1;
                    float g0 = c0 + z.x * kPDF * __expf(-0.5f * z.x * z.x);
                    float g1 = c1 + z.y * kPDF * __expf(-0.5f * z.y * z.y);
                    vd[2 * p]     = g0 * dz.x;
                    vd[2 * p + 1] = g1 * dz.y;
                }
                float* row = shA + (j0 + jj) * 36 + sb;
                *(float4*)(row)      = make_float4(va[0], va[1], va[2], va[3]);
                *(float4*)(row + 16) = make_float4(vd[0], vd[1], vd[2], vd[3]);
            }
            __syncthreads();

            // ---- layer 2: z2 = a1@W2 + b2 ; dz2 = d1@W2 ----
            #pragma unroll
            for (int jj = 0; jj < 2; jj++) {
                float bb = shB2[j0 + jj];
                u64 bp = pk2(bb, bb);
                #pragma unroll
                for (int p = 0; p < 2; p++) { aA[jj][p] = bp; aD[jj][p] = 0ull; }
            }
            #pragma unroll 8
            for (int k = 0; k < 192; k++) {
                const float* ar = shA + k * 36 + sb;
                ulonglong2 A0 = *(const ulonglong2*)ar;
                ulonglong2 E0 = *(const ulonglong2*)(ar + 16);
                float2 w = *(const float2*)(shW2 + k * 192 + j0);
                u64 w0 = pk2(w.x, w.x), w1 = pk2(w.y, w.y);
                fma2(aA[0][0], A0.x, w0); fma2(aA[0][1], A0.y, w0);
                fma2(aA[1][0], A0.x, w1); fma2(aA[1][1], A0.y, w1);
                fma2(aD[0][0], E0.x, w0); fma2(aD[0][1], E0.y, w0);
                fma2(aD[1][0], E0.x, w1); fma2(aD[1][1], E0.y, w1);
            }
            __syncthreads();   // all reads of a1d1 done; shA reused as a2t

            // GELU layer2: store a2 transposed; trace partial from d2 in regs
            float tp[4] = {0.f, 0.f, 0.f, 0.f};
            #pragma unroll
            for (int jj = 0; jj < 2; jj++) {
                #pragma unroll
                for (int p = 0; p < 2; p++) {
                    float2 z  = upk2(aA[jj][p]);
                    float2 dz = upk2(aD[jj][p]);
                    float c0 = 0.5f * (1.f + erff(z.x * kSQ));
                    float c1 = 0.5f * (1.f + erff(z.y * kSQ));
                    float a0 = z.x * c0, a1v = z.y * c1;
                    float g0 = c0 + z.x * kPDF * __expf(-0.5f * z.x * z.x);
                    float g1 = c1 + z.y * kPDF * __expf(-0.5f * z.y * z.y);
                    float d0 = g0 * dz.x, d1v = g1 * dz.y;
                    int ca = sb + 2 * p;
                    shA[(ca)     * 196 + j0 + jj] = a0;
                    shA[(ca + 1) * 196 + j0 + jj] = a1v;
                    float2 wv = upk2(aW[jj][p]);
                    tp[2 * p]     += d0  * wv.x;      // d2 . (W3 e)
                    tp[2 * p + 1] += d1v * wv.y;
                }
            }
            // warp butterfly reduce the 4 sample-partials (warp uniform in q)
            #pragma unroll
            for (int off = 16; off > 0; off >>= 1) {
                #pragma unroll
                for (int i = 0; i < 4; i++)
                    tp[i] += __shfl_xor_sync(0xFFFFFFFFu, tp[i], off);
            }
            if (lane == 0) {
                #pragma unroll
                for (int i = 0; i < 4; i++) shTW[wid * 4 + i] = tp[i];
            }
            __syncthreads();

            // ---- layer 3 (a-path only): f = a2 @ W3 (256 outputs) ----
            if (tid < 256) {
                int s = tid & 15, dd = tid >> 4;
                const float* ap = shA + s * 196;
                const float* wp = shW3t + dd * 192;
                float acc = 0.f;
                #pragma unroll 8
                for (int k = 0; k < 192; k += 4) {
                    float4 av = *(const float4*)(ap + k);
                    float4 wv = *(const float4*)(wp + k);
                    acc += av.x * wv.x + av.y * wv.y + av.z * wv.z + av.w * wv.w;
                }
                shFJ[s * 17 + dd] = acc;
            }
            __syncthreads();

            // ---- epilogue: f store / RK4 combine / trace accumulate ----
            float wst = (st == 1 || st == 2) ? 3.f : 1.f;
            if (tid < 256) {
                int i = tid;
                int s = es, d = ed;
                float f = shFJ[s * 17 + d] + shB3[d];
                if (st < 3) shFB[st * 256 + i] = f;
                else shY[i] += dtf * 0.125f *
                     (shFB[i] + 3.f * (shFB[256 + i] + shFB[512 + i]) + f);
            }
            if (tid < 16) {
                int s = tid;
                int qq = s >> 2, si = s & 3;
                float tr = shTW[(3 * qq) * 4 + si] + shTW[(3 * qq + 1) * 4 + si]
                         + shTW[(3 * qq + 2) * 4 + si];
                shTR[s] += wst * tr;
            }
            __syncthreads();
        }
    }

    // logp = -0.5*||z0||^2 - 8*log(2pi) - dlogp ;  dlogp = -dt/8 * sum(w*tr)
    if (tid < 16) {
        int s = tid;
        float ss = 0.f;
        #pragma unroll
        for (int d = 0; d < 16; d++) { float v = shY[s * 16 + d]; ss += v * v; }
        out[s0 + s] = -0.5f * ss - 14.703016531274763f + dtf * 0.125f * shTR[s];
    }
}

extern "C" void kernel_launch(void* const* d_in, const int* in_sizes, int n_in,
                              void* d_out, int out_size) {
    const float* theta = (const float*)d_in[0];
    const float* hg    = (const float*)d_in[1];
    const float* eps   = (const float*)d_in[2];
    const float* W1    = (const float*)d_in[3];
    const float* b1    = (const float*)d_in[4];
    const float* W2    = (const float*)d_in[5];
    const float* b2    = (const float*)d_in[6];
    const float* W3    = (const float*)d_in[7];
    const float* b3    = (const float*)d_in[8];
    float* out = (float*)d_out;

    cudaFuncSetAttribute(ConditionalCNF_27590869910221_kernel,
                         cudaFuncAttributeMaxDynamicSharedMemorySize,
                         SMEM_FLOATS * (int)sizeof(float));
    ConditionalCNF_27590869910221_kernel<<<B_TOT / TM, NTHR,
                                           SMEM_FLOATS * sizeof(float)>>>(
        theta, hg, eps, W1, b1, W2, b2, W3, b3, out);
}